// round 6
// baseline (speedup 1.0000x reference)
#include <cuda_runtime.h>
#include <cstdint>
#include <math.h>

// ============================================================================
// CustomAttention B=16, T=S=E=1024 fp32. mma.sync tf32 + cp.async 4-stage.
// (tcgen05 unavailable: harness emits compute_103 PTX -> no 'a' features.)
// Block tile 128(M) x 256(N) x 16(K), 256 threads, 8 warps of 64x64, 1 CTA/SM.
// Load-issue-bound regime: bigger tile cuts cp.async ops + L2 traffic by 25%.
// ============================================================================

#define LD1 20       // [m][k] / [n][k] smem row stride (floats)
#define LD2A 136     // [k][m] stride (A m-unit, 128 wide)
#define LD2B 264     // [k][n] stride (B n-unit, 256 wide)
#define B_OFF 2560               // floats (128*20)
#define STG_FLOATS 7680          // 2560 (A) + 5120 (B)
#define STG_BYTES 30720
#define NSTAGE 4
#define SMEM_BYTES (NSTAGE * STG_BYTES)   // 122880

// ---------------- scratch (device globals; no allocation allowed) -----------
__device__ float g_rq[16u * 1024u * 1024u];
__device__ float g_rk[16u * 1024u * 1024u];
__device__ float g_rv[16u * 1024u * 1024u];
__device__ float g_rw[4u * 1024u * 1024u];   // Wq|Wk|Wv|Wo rounded
__device__ float g_q [16u * 1024u * 1024u];
__device__ float g_k [16u * 1024u * 1024u];
__device__ float g_v [16u * 1024u * 1024u];
__device__ float g_w [16u * 1024u * 1024u];
__device__ float g_o [16u * 1024u * 1024u];

__device__ __forceinline__ float f2tf(float x) {
    unsigned u;
    asm("cvt.rna.tf32.f32 %0, %1;" : "=r"(u) : "f"(x));
    return __uint_as_float(u);
}
__device__ __forceinline__ void cpa16(uint32_t s, const float* g) {
    asm volatile("cp.async.cg.shared.global [%0], [%1], 16;"
                 :: "r"(s), "l"(g));
}
#define CP_COMMIT() asm volatile("cp.async.commit_group;")
#define CP_WAIT2()  asm volatile("cp.async.wait_group 2;")

__device__ __forceinline__ void mma8(float* d, const float* a, const float* b) {
    asm volatile(
        "mma.sync.aligned.m16n8k8.row.col.f32.tf32.tf32.f32 "
        "{%0,%1,%2,%3}, {%4,%5,%6,%7}, {%8,%9}, {%0,%1,%2,%3};"
        : "+f"(d[0]), "+f"(d[1]), "+f"(d[2]), "+f"(d[3])
        : "r"(__float_as_uint(a[0])), "r"(__float_as_uint(a[1])),
          "r"(__float_as_uint(a[2])), "r"(__float_as_uint(a[3])),
          "r"(__float_as_uint(b[0])), "r"(__float_as_uint(b[1])));
}

// ============================================================================
// Batched GEMM: C[z][m][n] = scale * sum_k A(m,k)*B(n,k) (+ bias[n])
//   AK1:  A(m,k) = A[m*sA + k]   else A(m,k) = A[k*sA + m]   (same for B)
// M mult of 128 (grid.y), N mult of 256 (grid.x), K = 1024. C row-major ldC.
// ============================================================================
template <bool AK1, bool BK1, bool BIAS, bool ROUND>
__global__ void __launch_bounds__(256, 1)
gemm_v5(const float* __restrict__ A, const float* __restrict__ B,
        const float* __restrict__ bias, float* __restrict__ C,
        long long bsA, long long bsB, long long bsC,
        int sA, int sB, int ldC, float scale) {
    extern __shared__ float sm[];
    const uint32_t smb = (uint32_t)__cvta_generic_to_shared(sm);

    const int tid  = threadIdx.x;           // 0..255
    const int lane = tid & 31;
    const int warp = tid >> 5;               // 0..7
    const int wm = (warp & 1) << 6;          // 0 / 64
    const int wn = (warp >> 1) << 6;         // 0 / 64 / 128 / 192
    const int gr = lane >> 2;
    const int kr = lane & 3;
    const int bn = blockIdx.x << 8;          // 256-wide N tile
    const int bm = blockIdx.y << 7;          // 128-wide M tile

    A += (long long)blockIdx.z * bsA;
    B += (long long)blockIdx.z * bsB;
    C += (long long)blockIdx.z * bsC;

    // ---- cp.async source pointers + smem byte offsets (A:2, B:4 chunks) ----
    const float* gA[2];
    const float* gB[4];
    uint32_t dA[2], dB[4];
    long long stepA, stepB;
    if (AK1) {
#pragma unroll
        for (int i = 0; i < 2; i++) {
            const int c = tid + (i << 8);
            const int m = c >> 2, kq = c & 3;
            gA[i] = A + (long long)(bm + m) * sA + 4 * kq;
            dA[i] = (uint32_t)(m * LD1 + 4 * kq) * 4u;
        }
        stepA = 16;
    } else {
#pragma unroll
        for (int i = 0; i < 2; i++) {
            const int c = tid + (i << 8);
            const int k = c >> 5, m4 = (c & 31) << 2;
            gA[i] = A + (long long)k * sA + bm + m4;
            dA[i] = (uint32_t)(k * LD2A + m4) * 4u;
        }
        stepA = 16LL * sA;
    }
    if (BK1) {
#pragma unroll
        for (int i = 0; i < 4; i++) {
            const int c = tid + (i << 8);
            const int n = c >> 2, kq = c & 3;
            gB[i] = B + (long long)(bn + n) * sB + 4 * kq;
            dB[i] = (uint32_t)(B_OFF + n * LD1 + 4 * kq) * 4u;
        }
        stepB = 16;
    } else {
#pragma unroll
        for (int i = 0; i < 4; i++) {
            const int c = tid + (i << 8);
            const int k = c >> 6, n4 = (c & 63) << 2;
            gB[i] = B + (long long)k * sB + bn + n4;
            dB[i] = (uint32_t)(B_OFF + k * LD2B + n4) * 4u;
        }
        stepB = 16LL * sB;
    }

    float acc[4][8][4];
#pragma unroll
    for (int i = 0; i < 4; i++)
#pragma unroll
        for (int j = 0; j < 8; j++)
#pragma unroll
            for (int l = 0; l < 4; l++) acc[i][j][l] = 0.f;

    // ---- prologue: stages 0..2 ----
#pragma unroll
    for (int s = 0; s < 3; s++) {
        const uint32_t sb = smb + s * STG_BYTES;
#pragma unroll
        for (int i = 0; i < 2; i++) { cpa16(sb + dA[i], gA[i]); gA[i] += stepA; }
#pragma unroll
        for (int i = 0; i < 4; i++) { cpa16(sb + dB[i], gB[i]); gB[i] += stepB; }
        CP_COMMIT();
    }

    // ---- main loop over 64 k-tiles ----
    for (int kt = 0; kt < 64; kt++) {
        CP_WAIT2();
        __syncthreads();

        if (kt + 3 < 64) {
            const uint32_t sb = smb + ((kt + 3) & 3) * STG_BYTES;
#pragma unroll
            for (int i = 0; i < 2; i++) { cpa16(sb + dA[i], gA[i]); gA[i] += stepA; }
#pragma unroll
            for (int i = 0; i < 4; i++) { cpa16(sb + dB[i], gB[i]); gB[i] += stepB; }
        }
        CP_COMMIT();

        const float* As = sm + (kt & 3) * STG_FLOATS;
        const float* Bs = As + B_OFF;
#pragma unroll
        for (int k8 = 0; k8 < 2; k8++) {
            float a[4][4], b[8][2];
            if (AK1) {
#pragma unroll
                for (int mt = 0; mt < 4; mt++) {
                    const float* p = As + (wm + mt * 16 + gr) * LD1 + k8 * 8 + kr;
                    a[mt][0] = p[0];
                    a[mt][1] = p[8 * LD1];
                    a[mt][2] = p[4];
                    a[mt][3] = p[8 * LD1 + 4];
                }
            } else {
#pragma unroll
                for (int mt = 0; mt < 4; mt++) {
                    const float* p = As + (k8 * 8 + kr) * LD2A + wm + mt * 16 + gr;
                    a[mt][0] = p[0];
                    a[mt][1] = p[8];
                    a[mt][2] = p[4 * LD2A];
                    a[mt][3] = p[4 * LD2A + 8];
                }
            }
            if (BK1) {
#pragma unroll
                for (int nt = 0; nt < 8; nt++) {
                    const float* p = Bs + (wn + nt * 8 + gr) * LD1 + k8 * 8 + kr;
                    b[nt][0] = p[0];
                    b[nt][1] = p[4];
                }
            } else {
#pragma unroll
                for (int nt = 0; nt < 8; nt++) {
                    const float* p = Bs + (k8 * 8 + kr) * LD2B + wn + nt * 8 + gr;
                    b[nt][0] = p[0];
                    b[nt][1] = p[4 * LD2B];
                }
            }
#pragma unroll
            for (int mt = 0; mt < 4; mt++)
#pragma unroll
                for (int nt = 0; nt < 8; nt++)
                    mma8(acc[mt][nt], a[mt], b[nt]);
        }
    }

    // ---- epilogue ----
#pragma unroll
    for (int mt = 0; mt < 4; mt++) {
        const long long r0 = (long long)(bm + wm + mt * 16 + gr) * ldC;
#pragma unroll
        for (int nt = 0; nt < 8; nt++) {
            const int col = bn + wn + nt * 8 + kr * 2;
            float b0 = 0.f, b1 = 0.f;
            if (BIAS) {
                float2 bb = *(const float2*)(bias + col);
                b0 = bb.x; b1 = bb.y;
            }
            float x0 = acc[mt][nt][0] * scale + b0;
            float x1 = acc[mt][nt][1] * scale + b1;
            float x2 = acc[mt][nt][2] * scale + b0;
            float x3 = acc[mt][nt][3] * scale + b1;
            if (ROUND) {
                x0 = f2tf(x0); x1 = f2tf(x1); x2 = f2tf(x2); x3 = f2tf(x3);
            }
            *(float2*)&C[r0 + col] = make_float2(x0, x1);
            *(float2*)&C[r0 + 8LL * ldC + col] = make_float2(x2, x3);
        }
    }
}

// ---------------- fused pre-round (RNA -> tf32), 3 big tensors --------------
__global__ void round3(const float* __restrict__ a, const float* __restrict__ b,
                       const float* __restrict__ c, float* __restrict__ oa,
                       float* __restrict__ ob, float* __restrict__ oc) {
    const int per = 16 * 1024 * 1024 / 1024;  // blocks per tensor (1024 fl/blk)
    const int t = blockIdx.x / per;
    const int i = (blockIdx.x % per) * 1024 + threadIdx.x * 4;
    const float* in = (t == 0) ? a : (t == 1) ? b : c;
    float* out = (t == 0) ? oa : (t == 1) ? ob : oc;
    float4 v = *(const float4*)(in + i);
    v.x = f2tf(v.x); v.y = f2tf(v.y); v.z = f2tf(v.z); v.w = f2tf(v.w);
    *(float4*)(out + i) = v;
}

// ---------------- fused pre-round for the 4 weight matrices ------------------
__global__ void round4w(const float* __restrict__ w0, const float* __restrict__ w1,
                        const float* __restrict__ w2, const float* __restrict__ w3,
                        float* __restrict__ out) {
    const int per = 1024 * 1024 / 1024;
    const int t = blockIdx.x / per;
    const int i = (blockIdx.x % per) * 1024 + threadIdx.x * 4;
    const float* in = (t == 0) ? w0 : (t == 1) ? w1 : (t == 2) ? w2 : w3;
    float4 v = *(const float4*)(in + i);
    v.x = f2tf(v.x); v.y = f2tf(v.y); v.z = f2tf(v.z); v.w = f2tf(v.w);
    *(float4*)(out + t * 1024 * 1024 + i) = v;
}

// ---------------- softmax over rows of 1024, in place, rounds output ---------
__device__ __forceinline__ float warpMax(float v) {
#pragma unroll
    for (int o = 16; o; o >>= 1) v = fmaxf(v, __shfl_xor_sync(0xffffffffu, v, o));
    return v;
}
__device__ __forceinline__ float warpSum(float v) {
#pragma unroll
    for (int o = 16; o; o >>= 1) v += __shfl_xor_sync(0xffffffffu, v, o);
    return v;
}
__global__ void softmax1024(float* __restrict__ W) {
    const long long row = blockIdx.x;
    float4* p = (float4*)(W + row * 1024);
    const int tid = threadIdx.x;  // 256
    float4 x = p[tid];
    float m = fmaxf(fmaxf(x.x, x.y), fmaxf(x.z, x.w));
    m = warpMax(m);
    __shared__ float sm[8], ss[8];
    if ((tid & 31) == 0) sm[tid >> 5] = m;
    __syncthreads();
    if (tid < 32) {
        float v = (tid < 8) ? sm[tid] : -1e30f;
        v = warpMax(v);
        if (tid == 0) sm[0] = v;
    }
    __syncthreads();
    m = sm[0];
    float e0 = __expf(x.x - m), e1 = __expf(x.y - m),
          e2 = __expf(x.z - m), e3 = __expf(x.w - m);
    float s = e0 + e1 + e2 + e3;
    s = warpSum(s);
    if ((tid & 31) == 0) ss[tid >> 5] = s;
    __syncthreads();
    if (tid < 32) {
        float v = (tid < 8) ? ss[tid] : 0.f;
        v = warpSum(v);
        if (tid == 0) ss[0] = v;
    }
    __syncthreads();
    const float inv = 1.0f / ss[0];
    p[tid] = make_float4(f2tf(e0 * inv), f2tf(e1 * inv),
                         f2tf(e2 * inv), f2tf(e3 * inv));
}

// ---------------- host side ---------------------------------------------------
extern "C" void kernel_launch(void* const* d_in, const int* in_sizes, int n_in,
                              void* d_out, int out_size) {
    const float* query = (const float*)d_in[0];
    const float* key   = (const float*)d_in[1];
    const float* value = (const float*)d_in[2];
    const float* Wq = (const float*)d_in[3];
    const float* bq = (const float*)d_in[4];
    const float* Wk = (const float*)d_in[5];
    const float* bk = (const float*)d_in[6];
    const float* Wv = (const float*)d_in[7];
    const float* bv = (const float*)d_in[8];
    const float* Wo = (const float*)d_in[9];
    const float* bo = (const float*)d_in[10];
    float* out = (float*)d_out;

    float *rq, *rk, *rv, *rw, *q, *k, *v, *w, *o;
    cudaGetSymbolAddress((void**)&rq, g_rq);
    cudaGetSymbolAddress((void**)&rk, g_rk);
    cudaGetSymbolAddress((void**)&rv, g_rv);
    cudaGetSymbolAddress((void**)&rw, g_rw);
    cudaGetSymbolAddress((void**)&q, g_q);
    cudaGetSymbolAddress((void**)&k, g_k);
    cudaGetSymbolAddress((void**)&v, g_v);
    cudaGetSymbolAddress((void**)&w, g_w);
    cudaGetSymbolAddress((void**)&o, g_o);

    cudaFuncSetAttribute(gemm_v5<true, true, true, true>,
                         cudaFuncAttributeMaxDynamicSharedMemorySize, SMEM_BYTES);
    cudaFuncSetAttribute(gemm_v5<false, true, false, false>,
                         cudaFuncAttributeMaxDynamicSharedMemorySize, SMEM_BYTES);
    cudaFuncSetAttribute(gemm_v5<true, false, false, true>,
                         cudaFuncAttributeMaxDynamicSharedMemorySize, SMEM_BYTES);
    cudaFuncSetAttribute(gemm_v5<true, true, true, false>,
                         cudaFuncAttributeMaxDynamicSharedMemorySize, SMEM_BYTES);

    // launches 1-2: fused rounding (also puts GEMMs at capture slots 3-6)
    round3<<<3 * 16384, 256>>>(query, key, value, rq, rk, rv);
    round4w<<<4 * 1024, 256>>>(Wq, Wk, Wv, Wo, rw);

    const long long MB = 1024LL * 1024LL;
    const int WSZ = 1024 * 1024;
    dim3 blk(256);
    dim3 gp(4, 128, 1);   // projections: N=1024 (4 tiles), M=16384 (128 tiles)
    dim3 ga(4, 8, 16);    // attention:   N=1024, M=1024, batch 16

    // q/k/v = X @ W^T + b (k-unit both), rounded outputs
    gemm_v5<true, true, true, true><<<gp, blk, SMEM_BYTES>>>(
        rq, rw + 0 * WSZ, bq, q, 0, 0, 0, 1024, 1024, 1024, 1.0f);
    gemm_v5<true, true, true, true><<<gp, blk, SMEM_BYTES>>>(
        rk, rw + 1 * WSZ, bk, k, 0, 0, 0, 1024, 1024, 1024, 1.0f);
    gemm_v5<true, true, true, true><<<gp, blk, SMEM_BYTES>>>(
        rv, rw + 2 * WSZ, bv, v, 0, 0, 0, 1024, 1024, 1024, 1.0f);

    // w[b,i,s] = (1/32) sum_t q[b,t,i]*k[b,s,t]: A=q m-unit, B=k k-unit
    gemm_v5<false, true, false, false><<<ga, blk, SMEM_BYTES>>>(
        q, k, nullptr, w, MB, MB, MB, 1024, 1024, 1024, 0.03125f);

    softmax1024<<<16 * 1024, 256>>>(w);

    // o[b,i,e] = sum_s a[b,i,s]*v[b,s,e]: A=w k-unit, B=v n-unit
    gemm_v5<true, false, false, true><<<ga, blk, SMEM_BYTES>>>(
        w, v, nullptr, o, MB, MB, MB, 1024, 1024, 1024, 1.0f);

    // out = o @ Wo^T + bo
    gemm_v5<true, true, true, false><<<gp, blk, SMEM_BYTES>>>(
        o, rw + 3 * WSZ, bo, out, 0, 0, 0, 1024, 1024, 1024, 1.0f);
}

// round 7
// speedup vs baseline: 1.3156x; 1.3156x over previous
#include <cuda_runtime.h>
#include <cstdint>
#include <math.h>

// ============================================================================
// CustomAttention B=16, T=S=E=1024 fp32. mma.sync tf32, cp.async 3-stage BK=32,
// ldmatrix fragments, all GEMMs K-major (q/v projections store transposed).
// 128-thread CTAs, block 128x128x32, 4 warps of 64x64, 2 CTAs/SM.
// ============================================================================

#define LDA 36                      // smem row stride (floats), K-major rows
#define LDB 36
#define AOP_BYTES (128 * LDA * 4)   // 18432
#define B_OFF_BYTES AOP_BYTES
#define STG_BYTES (2 * AOP_BYTES)   // 36864
#define SMEM_BYTES (3 * STG_BYTES)  // 110592

// ---------------- scratch (device globals; no allocation allowed) -----------
__device__ float g_rin[48u * 1024u * 1024u];  // rounded query|key|value
__device__ float g_rw [4u * 1024u * 1024u];   // rounded Wq|Wk|Wv|Wo
__device__ float g_bias[3 * 1024];            // bq|bk|bv
__device__ float g_q [16u * 1024u * 1024u];   // qT[i][b*1024+t]  (ld 16384)
__device__ float g_k [16u * 1024u * 1024u];   // k[b*1024+s][t]   (ld 1024)
__device__ float g_v [16u * 1024u * 1024u];   // vT[e][b*1024+s]  (ld 16384)
__device__ float g_w [16u * 1024u * 1024u];
__device__ float g_o [16u * 1024u * 1024u];

__device__ __forceinline__ float f2tf(float x) {
    unsigned u;
    asm("cvt.rna.tf32.f32 %0, %1;" : "=r"(u) : "f"(x));
    return __uint_as_float(u);
}
__device__ __forceinline__ void cpa16(uint32_t s, const float* g) {
    asm volatile("cp.async.cg.shared.global [%0], [%1], 16;" :: "r"(s), "l"(g));
}
#define CP_COMMIT() asm volatile("cp.async.commit_group;")
#define CP_WAIT1()  asm volatile("cp.async.wait_group 1;")

__device__ __forceinline__ void ldsm4(uint32_t* r, uint32_t addr) {
    asm volatile("ldmatrix.sync.aligned.m8n8.x4.shared.b16 {%0,%1,%2,%3}, [%4];"
                 : "=r"(r[0]), "=r"(r[1]), "=r"(r[2]), "=r"(r[3]) : "r"(addr));
}
__device__ __forceinline__ void mma8(float* d, const uint32_t* a,
                                     const uint32_t* b) {
    asm volatile(
        "mma.sync.aligned.m16n8k8.row.col.f32.tf32.tf32.f32 "
        "{%0,%1,%2,%3}, {%4,%5,%6,%7}, {%8,%9}, {%0,%1,%2,%3};"
        : "+f"(d[0]), "+f"(d[1]), "+f"(d[2]), "+f"(d[3])
        : "r"(a[0]), "r"(a[1]), "r"(a[2]), "r"(a[3]), "r"(b[0]), "r"(b[1]));
}

// ---------------- shared mainloop: 128x128 tile, K=1024, all K-major --------
// At = A + bm*sA (rows m, k contiguous); Bt = B + bn*sB (rows n, k contiguous)
__device__ __forceinline__ void gemm_main(const float* __restrict__ At,
                                          const float* __restrict__ Bt,
                                          int sA, int sB, float* sm,
                                          float (&acc)[4][8][4]) {
    const uint32_t smb = (uint32_t)__cvta_generic_to_shared(sm);
    const int tid = threadIdx.x, lane = tid & 31, warp = tid >> 5;
    const int wm = (warp & 1) << 6, wn = (warp >> 1) << 6;

    // cp.async lanes: each thread: row = tid>>3 (+16*i), quad = (tid&7)*4
    const int rq = tid >> 3, qq = (tid & 7) << 2;
    const float* gA = At + (long long)rq * sA + qq;
    const float* gB = Bt + (long long)rq * sB + qq;
    const uint32_t saA = smb + (uint32_t)(rq * LDA + qq) * 4u;
    const uint32_t saB = smb + B_OFF_BYTES + (uint32_t)(rq * LDB + qq) * 4u;

    // LDSM lane addressing
    const int seg = lane >> 3, li = lane & 7;
    const uint32_t aLane =
        smb + (uint32_t)((wm + ((seg & 1) << 3) + li) * LDA + ((seg >> 1) << 2)) * 4u;
    const uint32_t bLane =
        smb + B_OFF_BYTES +
        (uint32_t)((wn + ((seg >> 1) << 3) + li) * LDB + ((seg & 1) << 2)) * 4u;

    // prologue: stages 0,1
#pragma unroll
    for (int s = 0; s < 2; s++) {
        const uint32_t st = s * STG_BYTES;
        const int k0 = s * 32;
#pragma unroll
        for (int i = 0; i < 8; i++) {
            cpa16(saA + st + i * (16 * LDA * 4), gA + k0 + i * 16LL * sA);
            cpa16(saB + st + i * (16 * LDB * 4), gB + k0 + i * 16LL * sB);
        }
        CP_COMMIT();
    }

    int bufc = 0, bufp = 2;
    for (int kt = 0; kt < 32; kt++) {
        CP_WAIT1();
        __syncthreads();

        if (kt + 2 < 32) {
            const uint32_t st = bufp * STG_BYTES;
            const int k0 = (kt + 2) * 32;
#pragma unroll
            for (int i = 0; i < 8; i++) {
                cpa16(saA + st + i * (16 * LDA * 4), gA + k0 + i * 16LL * sA);
                cpa16(saB + st + i * (16 * LDB * 4), gB + k0 + i * 16LL * sB);
            }
        }
        CP_COMMIT();

        const uint32_t stg = bufc * STG_BYTES;
#pragma unroll
        for (int k8 = 0; k8 < 4; k8++) {
            uint32_t a[4][4], bb[4][4];
#pragma unroll
            for (int mt = 0; mt < 4; mt++)
                ldsm4(a[mt], aLane + stg + mt * (16 * LDA * 4) + k8 * 32);
#pragma unroll
            for (int p = 0; p < 4; p++)
                ldsm4(bb[p], bLane + stg + p * (16 * LDB * 4) + k8 * 32);
#pragma unroll
            for (int mt = 0; mt < 4; mt++)
#pragma unroll
                for (int nt = 0; nt < 8; nt++)
                    mma8(acc[mt][nt], a[mt], &bb[nt >> 1][(nt & 1) << 1]);
        }
        if (++bufc == 3) bufc = 0;
        if (++bufp == 3) bufp = 0;
    }
}

// ---------------- standard GEMM: C[z][m][n] = scale*A.B^T (+bias) -----------
template <bool BIAS, bool ROUND>
__global__ void __launch_bounds__(128, 2)
gemm_k(const float* __restrict__ A, const float* __restrict__ B,
       const float* __restrict__ bias, float* __restrict__ C,
       long long bsA, long long bsB, long long bsC,
       int sA, int sB, int ldC, float scale) {
    extern __shared__ float sm[];
    const int bn = blockIdx.x << 7, bm = blockIdx.y << 7, z = blockIdx.z;
    const float* At = A + (long long)z * bsA + (long long)bm * sA;
    const float* Bt = B + (long long)z * bsB + (long long)bn * sB;

    float acc[4][8][4];
#pragma unroll
    for (int i = 0; i < 4; i++)
#pragma unroll
        for (int j = 0; j < 8; j++)
#pragma unroll
            for (int l = 0; l < 4; l++) acc[i][j][l] = 0.f;

    gemm_main(At, Bt, sA, sB, sm, acc);

    float* Cz = C + (long long)z * bsC;
    const int lane = threadIdx.x & 31, warp = threadIdx.x >> 5;
    const int wm = (warp & 1) << 6, wn = (warp >> 1) << 6;
    const int gr = lane >> 2, kr = lane & 3;
#pragma unroll
    for (int mt = 0; mt < 4; mt++) {
        const long long r0 = (long long)(bm + wm + mt * 16 + gr) * ldC;
#pragma unroll
        for (int nt = 0; nt < 8; nt++) {
            const int col = bn + wn + nt * 8 + kr * 2;
            float b0 = 0.f, b1 = 0.f;
            if (BIAS) {
                float2 bb = *(const float2*)(bias + col);
                b0 = bb.x; b1 = bb.y;
            }
            float x0 = acc[mt][nt][0] * scale + b0;
            float x1 = acc[mt][nt][1] * scale + b1;
            float x2 = acc[mt][nt][2] * scale + b0;
            float x3 = acc[mt][nt][3] * scale + b1;
            if (ROUND) { x0 = f2tf(x0); x1 = f2tf(x1); x2 = f2tf(x2); x3 = f2tf(x3); }
            *(float2*)&Cz[r0 + col] = make_float2(x0, x1);
            *(float2*)&Cz[r0 + 8LL * ldC + col] = make_float2(x2, x3);
        }
    }
}

// ---------------- fused QKV projection: z=0 qT, z=1 k, z=2 vT ----------------
__global__ void __launch_bounds__(128, 2)
gemm_qkv(const float* __restrict__ Ain, const float* __restrict__ W,
         const float* __restrict__ biases,
         float* __restrict__ Cq, float* __restrict__ Ck, float* __restrict__ Cv) {
    extern __shared__ float sm[];
    const int bn = blockIdx.x << 7, bm = blockIdx.y << 7, z = blockIdx.z;
    const float* At = Ain + (long long)z * (16LL << 20) + (long long)bm * 1024;
    const float* Bt = W + (long long)z * (1LL << 20) + (long long)bn * 1024;
    const float* bias = biases + z * 1024;

    float acc[4][8][4];
#pragma unroll
    for (int i = 0; i < 4; i++)
#pragma unroll
        for (int j = 0; j < 8; j++)
#pragma unroll
            for (int l = 0; l < 4; l++) acc[i][j][l] = 0.f;

    gemm_main(At, Bt, 1024, 1024, sm, acc);

    const int lane = threadIdx.x & 31, warp = threadIdx.x >> 5;
    const int wm = (warp & 1) << 6, wn = (warp >> 1) << 6;
    const int gr = lane >> 2, kr = lane & 3;

    if (z == 1) {  // normal store: k[m][n], ld 1024
#pragma unroll
        for (int mt = 0; mt < 4; mt++) {
            const long long r0 = (long long)(bm + wm + mt * 16 + gr) * 1024;
#pragma unroll
            for (int nt = 0; nt < 8; nt++) {
                const int col = bn + wn + nt * 8 + kr * 2;
                float2 bb = *(const float2*)(bias + col);
                float x0 = f2tf(acc[mt][nt][0] + bb.x);
                float x1 = f2tf(acc[mt][nt][1] + bb.y);
                float x2 = f2tf(acc[mt][nt][2] + bb.x);
                float x3 = f2tf(acc[mt][nt][3] + bb.y);
                *(float2*)&Ck[r0 + col] = make_float2(x0, x1);
                *(float2*)&Ck[r0 + 8LL * 1024 + col] = make_float2(x2, x3);
            }
        }
    } else {       // transposed store: CT[n][m], ld 16384
        float* CT = (z == 0) ? Cq : Cv;
#pragma unroll
        for (int mt = 0; mt < 4; mt++) {
            const int row = bm + wm + mt * 16 + gr;
#pragma unroll
            for (int nt = 0; nt < 8; nt++) {
                const int col = bn + wn + nt * 8 + kr * 2;
                float2 bb = *(const float2*)(bias + col);
                float x0 = f2tf(acc[mt][nt][0] + bb.x);
                float x1 = f2tf(acc[mt][nt][1] + bb.y);
                float x2 = f2tf(acc[mt][nt][2] + bb.x);
                float x3 = f2tf(acc[mt][nt][3] + bb.y);
                CT[(long long)col * 16384 + row] = x0;
                CT[(long long)(col + 1) * 16384 + row] = x1;
                CT[(long long)col * 16384 + row + 8] = x2;
                CT[(long long)(col + 1) * 16384 + row + 8] = x3;
            }
        }
    }
}

// ---------------- pre-round kernels -----------------------------------------
__global__ void round3(const float* __restrict__ a, const float* __restrict__ b,
                       const float* __restrict__ c, float* __restrict__ out) {
    const int per = 16 * 1024 * 1024 / 1024;
    const int t = blockIdx.x / per;
    const int i = (blockIdx.x % per) * 1024 + threadIdx.x * 4;
    const float* in = (t == 0) ? a : (t == 1) ? b : c;
    float4 v = *(const float4*)(in + i);
    v.x = f2tf(v.x); v.y = f2tf(v.y); v.z = f2tf(v.z); v.w = f2tf(v.w);
    *(float4*)(out + (long long)t * (16LL << 20) + i) = v;
}
__global__ void round4w(const float* __restrict__ w0, const float* __restrict__ w1,
                        const float* __restrict__ w2, const float* __restrict__ w3,
                        float* __restrict__ out) {
    const int per = 1024 * 1024 / 1024;
    const int t = blockIdx.x / per;
    const int i = (blockIdx.x % per) * 1024 + threadIdx.x * 4;
    const float* in = (t == 0) ? w0 : (t == 1) ? w1 : (t == 2) ? w2 : w3;
    float4 v = *(const float4*)(in + i);
    v.x = f2tf(v.x); v.y = f2tf(v.y); v.z = f2tf(v.z); v.w = f2tf(v.w);
    *(float4*)(out + t * 1024 * 1024 + i) = v;
}
__global__ void copy_bias(const float* __restrict__ b0, const float* __restrict__ b1,
                          const float* __restrict__ b2, float* __restrict__ dst) {
    int i = blockIdx.x * blockDim.x + threadIdx.x;   // 3072 threads
    const float* s = (i < 1024) ? b0 : (i < 2048) ? b1 : b2;
    dst[i] = s[i & 1023];
}

// ---------------- softmax over rows of 1024, in place, rounds output ---------
__device__ __forceinline__ float warpMax(float v) {
#pragma unroll
    for (int o = 16; o; o >>= 1) v = fmaxf(v, __shfl_xor_sync(0xffffffffu, v, o));
    return v;
}
__device__ __forceinline__ float warpSum(float v) {
#pragma unroll
    for (int o = 16; o; o >>= 1) v += __shfl_xor_sync(0xffffffffu, v, o);
    return v;
}
__global__ void softmax1024(float* __restrict__ W) {
    const long long row = blockIdx.x;
    float4* p = (float4*)(W + row * 1024);
    const int tid = threadIdx.x;  // 256
    float4 x = p[tid];
    float m = fmaxf(fmaxf(x.x, x.y), fmaxf(x.z, x.w));
    m = warpMax(m);
    __shared__ float sm[8], ss[8];
    if ((tid & 31) == 0) sm[tid >> 5] = m;
    __syncthreads();
    if (tid < 32) {
        float v = (tid < 8) ? sm[tid] : -1e30f;
        v = warpMax(v);
        if (tid == 0) sm[0] = v;
    }
    __syncthreads();
    m = sm[0];
    float e0 = __expf(x.x - m), e1 = __expf(x.y - m),
          e2 = __expf(x.z - m), e3 = __expf(x.w - m);
    float s = e0 + e1 + e2 + e3;
    s = warpSum(s);
    if ((tid & 31) == 0) ss[tid >> 5] = s;
    __syncthreads();
    if (tid < 32) {
        float v = (tid < 8) ? ss[tid] : 0.f;
        v = warpSum(v);
        if (tid == 0) ss[0] = v;
    }
    __syncthreads();
    const float inv = 1.0f / ss[0];
    p[tid] = make_float4(f2tf(e0 * inv), f2tf(e1 * inv),
                         f2tf(e2 * inv), f2tf(e3 * inv));
}

// ---------------- host side ---------------------------------------------------
extern "C" void kernel_launch(void* const* d_in, const int* in_sizes, int n_in,
                              void* d_out, int out_size) {
    const float* query = (const float*)d_in[0];
    const float* key   = (const float*)d_in[1];
    const float* value = (const float*)d_in[2];
    const float* Wq = (const float*)d_in[3];
    const float* bq = (const float*)d_in[4];
    const float* Wk = (const float*)d_in[5];
    const float* bk = (const float*)d_in[6];
    const float* Wv = (const float*)d_in[7];
    const float* bv = (const float*)d_in[8];
    const float* Wo = (const float*)d_in[9];
    const float* bo = (const float*)d_in[10];
    float* out = (float*)d_out;

    float *rin, *rw, *bias, *q, *k, *v, *w, *o;
    cudaGetSymbolAddress((void**)&rin, g_rin);
    cudaGetSymbolAddress((void**)&rw, g_rw);
    cudaGetSymbolAddress((void**)&bias, g_bias);
    cudaGetSymbolAddress((void**)&q, g_q);
    cudaGetSymbolAddress((void**)&k, g_k);
    cudaGetSymbolAddress((void**)&v, g_v);
    cudaGetSymbolAddress((void**)&w, g_w);
    cudaGetSymbolAddress((void**)&o, g_o);

    cudaFuncSetAttribute(gemm_qkv,
                         cudaFuncAttributeMaxDynamicSharedMemorySize, SMEM_BYTES);
    cudaFuncSetAttribute(gemm_k<false, false>,
                         cudaFuncAttributeMaxDynamicSharedMemorySize, SMEM_BYTES);
    cudaFuncSetAttribute(gemm_k<false, true>,
                         cudaFuncAttributeMaxDynamicSharedMemorySize, SMEM_BYTES);
    cudaFuncSetAttribute(gemm_k<true, false>,
                         cudaFuncAttributeMaxDynamicSharedMemorySize, SMEM_BYTES);

    round3<<<3 * 16384, 256>>>(query, key, value, rin);
    round4w<<<4 * 1024, 256>>>(Wq, Wk, Wv, Wo, rw);
    copy_bias<<<12, 256>>>(bq, bk, bv, bias);

    const long long MB = 1024LL * 1024LL;
    dim3 blk(128);

    // fused q/k/v projections (q,v transposed outputs)
    gemm_qkv<<<dim3(8, 128, 3), blk, SMEM_BYTES>>>(rin, rw, bias, q, k, v);

    // logits: w[b,i,s] = (1/32) sum_t qT[i, b*1024+t] * k[b*1024+s, t]
    gemm_k<false, false><<<dim3(8, 8, 16), blk, SMEM_BYTES>>>(
        q, k, nullptr, w, 1024, MB, MB, 16384, 1024, 1024, 0.03125f);

    softmax1024<<<16 * 1024, 256>>>(w);

    // o[b,i,e] = sum_s a[b,i,s] * vT[e, b*1024+s]
    gemm_k<false, true><<<dim3(8, 8, 16), blk, SMEM_BYTES>>>(
        w, v, nullptr, o, MB, 1024, MB, 1024, 16384, 1024, 1.0f);

    // out = o @ Wo^T + bo
    gemm_k<true, false><<<dim3(8, 128, 1), blk, SMEM_BYTES>>>(
        o, rw + 3 * MB, bo, out, 0, 0, 0, 1024, 1024, 1024, 1.0f);
}

// round 8
// speedup vs baseline: 1.3961x; 1.0612x over previous
#include <cuda_runtime.h>
#include <cstdint>
#include <math.h>

// ============================================================================
// CustomAttention B=16, T=S=E=1024 fp32. mma.sync tf32, cp.async 3-stage BK=32,
// ldmatrix fragments, all GEMMs K-major (q/v projections store transposed).
// 256-thread CTAs, block 128x128x32, 8 warps of 64x32, 2 CTAs/SM (16 warps/SM).
// ============================================================================

#define LDA 36                      // smem row stride (floats), K-major rows
#define LDB 36
#define AOP_BYTES (128 * LDA * 4)   // 18432
#define B_OFF_BYTES AOP_BYTES
#define STG_BYTES (2 * AOP_BYTES)   // 36864
#define SMEM_BYTES (3 * STG_BYTES)  // 110592

// ---------------- scratch (device globals; no allocation allowed) -----------
__device__ float g_rin[48u * 1024u * 1024u];  // rounded query|key|value
__device__ float g_rw [4u * 1024u * 1024u];   // rounded Wq|Wk|Wv|Wo
__device__ float g_bias[3 * 1024];            // bq|bk|bv
__device__ float g_q [16u * 1024u * 1024u];   // qT[i][b*1024+t]  (ld 16384)
__device__ float g_k [16u * 1024u * 1024u];   // k[b*1024+s][t]   (ld 1024)
__device__ float g_v [16u * 1024u * 1024u];   // vT[e][b*1024+s]  (ld 16384)
__device__ float g_w [16u * 1024u * 1024u];
__device__ float g_o [16u * 1024u * 1024u];

__device__ __forceinline__ float f2tf(float x) {
    unsigned u;
    asm("cvt.rna.tf32.f32 %0, %1;" : "=r"(u) : "f"(x));
    return __uint_as_float(u);
}
__device__ __forceinline__ void cpa16(uint32_t s, const float* g) {
    asm volatile("cp.async.cg.shared.global [%0], [%1], 16;" :: "r"(s), "l"(g));
}
#define CP_COMMIT() asm volatile("cp.async.commit_group;")
#define CP_WAIT1()  asm volatile("cp.async.wait_group 1;")

__device__ __forceinline__ void ldsm4(uint32_t* r, uint32_t addr) {
    asm volatile("ldmatrix.sync.aligned.m8n8.x4.shared.b16 {%0,%1,%2,%3}, [%4];"
                 : "=r"(r[0]), "=r"(r[1]), "=r"(r[2]), "=r"(r[3]) : "r"(addr));
}
__device__ __forceinline__ void mma8(float* d, const uint32_t* a,
                                     const uint32_t* b) {
    asm volatile(
        "mma.sync.aligned.m16n8k8.row.col.f32.tf32.tf32.f32 "
        "{%0,%1,%2,%3}, {%4,%5,%6,%7}, {%8,%9}, {%0,%1,%2,%3};"
        : "+f"(d[0]), "+f"(d[1]), "+f"(d[2]), "+f"(d[3])
        : "r"(a[0]), "r"(a[1]), "r"(a[2]), "r"(a[3]), "r"(b[0]), "r"(b[1]));
}

// ---------------- shared mainloop: 128x128 tile, K=1024, all K-major --------
// At = A + bm*sA (rows m, k contiguous); Bt = B + bn*sB (rows n, k contiguous)
// 256 threads: 8 warps, warp tile 64(M) x 32(N).
__device__ __forceinline__ void gemm_main(const float* __restrict__ At,
                                          const float* __restrict__ Bt,
                                          int sA, int sB, float* sm,
                                          float (&acc)[4][4][4]) {
    const uint32_t smb = (uint32_t)__cvta_generic_to_shared(sm);
    const int tid = threadIdx.x, lane = tid & 31, warp = tid >> 5;
    const int wm = (warp & 1) << 6;        // 0 / 64
    const int wn = (warp >> 1) << 5;       // 0 / 32 / 64 / 96

    // cp.async lanes: row = tid>>3 (+32*i), quad = (tid&7)*4 floats
    const int rq = tid >> 3, qq = (tid & 7) << 2;
    const float* gA = At + (long long)rq * sA + qq;
    const float* gB = Bt + (long long)rq * sB + qq;
    const uint32_t saA = smb + (uint32_t)(rq * LDA + qq) * 4u;
    const uint32_t saB = smb + B_OFF_BYTES + (uint32_t)(rq * LDB + qq) * 4u;

    // LDSM lane addressing (8x8 b16 matrices over f32 data)
    const int seg = lane >> 3, li = lane & 7;
    const uint32_t aLane =
        smb + (uint32_t)((wm + ((seg & 1) << 3) + li) * LDA + ((seg >> 1) << 2)) * 4u;
    const uint32_t bLane =
        smb + B_OFF_BYTES +
        (uint32_t)((wn + ((seg >> 1) << 3) + li) * LDB + ((seg & 1) << 2)) * 4u;

    // prologue: stages 0,1
#pragma unroll
    for (int s = 0; s < 2; s++) {
        const uint32_t st = s * STG_BYTES;
        const int k0 = s * 32;
#pragma unroll
        for (int i = 0; i < 4; i++) {
            cpa16(saA + st + i * (32 * LDA * 4), gA + k0 + i * 32LL * sA);
            cpa16(saB + st + i * (32 * LDB * 4), gB + k0 + i * 32LL * sB);
        }
        CP_COMMIT();
    }

    int bufc = 0, bufp = 2;
    for (int kt = 0; kt < 32; kt++) {
        CP_WAIT1();
        __syncthreads();

        if (kt + 2 < 32) {
            const uint32_t st = bufp * STG_BYTES;
            const int k0 = (kt + 2) * 32;
#pragma unroll
            for (int i = 0; i < 4; i++) {
                cpa16(saA + st + i * (32 * LDA * 4), gA + k0 + i * 32LL * sA);
                cpa16(saB + st + i * (32 * LDB * 4), gB + k0 + i * 32LL * sB);
            }
        }
        CP_COMMIT();

        const uint32_t stg = bufc * STG_BYTES;
#pragma unroll
        for (int k8 = 0; k8 < 4; k8++) {
            uint32_t a[4][4], bb[2][4];
#pragma unroll
            for (int mt = 0; mt < 4; mt++)
                ldsm4(a[mt], aLane + stg + mt * (16 * LDA * 4) + k8 * 32);
#pragma unroll
            for (int p = 0; p < 2; p++)
                ldsm4(bb[p], bLane + stg + p * (16 * LDB * 4) + k8 * 32);
#pragma unroll
            for (int mt = 0; mt < 4; mt++)
#pragma unroll
                for (int nt = 0; nt < 4; nt++)
                    mma8(acc[mt][nt], a[mt], &bb[nt >> 1][(nt & 1) << 1]);
        }
        if (++bufc == 3) bufc = 0;
        if (++bufp == 3) bufp = 0;
    }
}

// ---------------- standard GEMM: C[z][m][n] = scale*A.B^T (+bias) -----------
template <bool BIAS, bool ROUND>
__global__ void __launch_bounds__(256, 2)
gemm_k(const float* __restrict__ A, const float* __restrict__ B,
       const float* __restrict__ bias, float* __restrict__ C,
       long long bsA, long long bsB, long long bsC,
       int sA, int sB, int ldC, float scale) {
    extern __shared__ float sm[];
    const int bn = blockIdx.x << 7, bm = blockIdx.y << 7, z = blockIdx.z;
    const float* At = A + (long long)z * bsA + (long long)bm * sA;
    const float* Bt = B + (long long)z * bsB + (long long)bn * sB;

    float acc[4][4][4];
#pragma unroll
    for (int i = 0; i < 4; i++)
#pragma unroll
        for (int j = 0; j < 4; j++)
#pragma unroll
            for (int l = 0; l < 4; l++) acc[i][j][l] = 0.f;

    gemm_main(At, Bt, sA, sB, sm, acc);

    float* Cz = C + (long long)z * bsC;
    const int lane = threadIdx.x & 31, warp = threadIdx.x >> 5;
    const int wm = (warp & 1) << 6, wn = (warp >> 1) << 5;
    const int gr = lane >> 2, kr = lane & 3;
#pragma unroll
    for (int mt = 0; mt < 4; mt++) {
        const long long r0 = (long long)(bm + wm + mt * 16 + gr) * ldC;
#pragma unroll
        for (int nt = 0; nt < 4; nt++) {
            const int col = bn + wn + nt * 8 + kr * 2;
            float b0 = 0.f, b1 = 0.f;
            if (BIAS) {
                float2 bb = *(const float2*)(bias + col);
                b0 = bb.x; b1 = bb.y;
            }
            float x0 = acc[mt][nt][0] * scale + b0;
            float x1 = acc[mt][nt][1] * scale + b1;
            float x2 = acc[mt][nt][2] * scale + b0;
            float x3 = acc[mt][nt][3] * scale + b1;
            if (ROUND) { x0 = f2tf(x0); x1 = f2tf(x1); x2 = f2tf(x2); x3 = f2tf(x3); }
            *(float2*)&Cz[r0 + col] = make_float2(x0, x1);
            *(float2*)&Cz[r0 + 8LL * ldC + col] = make_float2(x2, x3);
        }
    }
}

// ---------------- fused QKV projection: z=0 qT, z=1 k, z=2 vT ----------------
__global__ void __launch_bounds__(256, 2)
gemm_qkv(const float* __restrict__ Ain, const float* __restrict__ W,
         const float* __restrict__ biases,
         float* __restrict__ Cq, float* __restrict__ Ck, float* __restrict__ Cv) {
    extern __shared__ float sm[];
    const int bn = blockIdx.x << 7, bm = blockIdx.y << 7, z = blockIdx.z;
    const float* At = Ain + (long long)z * (16LL << 20) + (long long)bm * 1024;
    const float* Bt = W + (long long)z * (1LL << 20) + (long long)bn * 1024;
    const float* bias = biases + z * 1024;

    float acc[4][4][4];
#pragma unroll
    for (int i = 0; i < 4; i++)
#pragma unroll
        for (int j = 0; j < 4; j++)
#pragma unroll
            for (int l = 0; l < 4; l++) acc[i][j][l] = 0.f;

    gemm_main(At, Bt, 1024, 1024, sm, acc);

    const int lane = threadIdx.x & 31, warp = threadIdx.x >> 5;
    const int wm = (warp & 1) << 6, wn = (warp >> 1) << 5;
    const int gr = lane >> 2, kr = lane & 3;

    if (z == 1) {  // normal store: k[m][n], ld 1024
#pragma unroll
        for (int mt = 0; mt < 4; mt++) {
            const long long r0 = (long long)(bm + wm + mt * 16 + gr) * 1024;
#pragma unroll
            for (int nt = 0; nt < 4; nt++) {
                const int col = bn + wn + nt * 8 + kr * 2;
                float2 bb = *(const float2*)(bias + col);
                float x0 = f2tf(acc[mt][nt][0] + bb.x);
                float x1 = f2tf(acc[mt][nt][1] + bb.y);
                float x2 = f2tf(acc[mt][nt][2] + bb.x);
                float x3 = f2tf(acc[mt][nt][3] + bb.y);
                *(float2*)&Ck[r0 + col] = make_float2(x0, x1);
                *(float2*)&Ck[r0 + 8LL * 1024 + col] = make_float2(x2, x3);
            }
        }
    } else {       // transposed store: CT[n][m], ld 16384
        float* CT = (z == 0) ? Cq : Cv;
#pragma unroll
        for (int mt = 0; mt < 4; mt++) {
            const int row = bm + wm + mt * 16 + gr;
#pragma unroll
            for (int nt = 0; nt < 4; nt++) {
                const int col = bn + wn + nt * 8 + kr * 2;
                float2 bb = *(const float2*)(bias + col);
                float x0 = f2tf(acc[mt][nt][0] + bb.x);
                float x1 = f2tf(acc[mt][nt][1] + bb.y);
                float x2 = f2tf(acc[mt][nt][2] + bb.x);
                float x3 = f2tf(acc[mt][nt][3] + bb.y);
                CT[(long long)col * 16384 + row] = x0;
                CT[(long long)(col + 1) * 16384 + row] = x1;
                CT[(long long)col * 16384 + row + 8] = x2;
                CT[(long long)(col + 1) * 16384 + row + 8] = x3;
            }
        }
    }
}

// ---------------- pre-round kernels -----------------------------------------
__global__ void round3(const float* __restrict__ a, const float* __restrict__ b,
                       const float* __restrict__ c, float* __restrict__ out) {
    const int per = 16 * 1024 * 1024 / 1024;
    const int t = blockIdx.x / per;
    const int i = (blockIdx.x % per) * 1024 + threadIdx.x * 4;
    const float* in = (t == 0) ? a : (t == 1) ? b : c;
    float4 v = *(const float4*)(in + i);
    v.x = f2tf(v.x); v.y = f2tf(v.y); v.z = f2tf(v.z); v.w = f2tf(v.w);
    *(float4*)(out + (long long)t * (16LL << 20) + i) = v;
}
__global__ void round4w(const float* __restrict__ w0, const float* __restrict__ w1,
                        const float* __restrict__ w2, const float* __restrict__ w3,
                        float* __restrict__ out) {
    const int per = 1024 * 1024 / 1024;
    const int t = blockIdx.x / per;
    const int i = (blockIdx.x % per) * 1024 + threadIdx.x * 4;
    const float* in = (t == 0) ? w0 : (t == 1) ? w1 : (t == 2) ? w2 : w3;
    float4 v = *(const float4*)(in + i);
    v.x = f2tf(v.x); v.y = f2tf(v.y); v.z = f2tf(v.z); v.w = f2tf(v.w);
    *(float4*)(out + t * 1024 * 1024 + i) = v;
}
__global__ void copy_bias(const float* __restrict__ b0, const float* __restrict__ b1,
                          const float* __restrict__ b2, float* __restrict__ dst) {
    int i = blockIdx.x * blockDim.x + threadIdx.x;   // 3072 threads
    const float* s = (i < 1024) ? b0 : (i < 2048) ? b1 : b2;
    dst[i] = s[i & 1023];
}

// ---------------- softmax over rows of 1024, in place, rounds output ---------
__device__ __forceinline__ float warpMax(float v) {
#pragma unroll
    for (int o = 16; o; o >>= 1) v = fmaxf(v, __shfl_xor_sync(0xffffffffu, v, o));
    return v;
}
__device__ __forceinline__ float warpSum(float v) {
#pragma unroll
    for (int o = 16; o; o >>= 1) v += __shfl_xor_sync(0xffffffffu, v, o);
    return v;
}
__global__ void softmax1024(float* __restrict__ W) {
    const long long row = blockIdx.x;
    float4* p = (float4*)(W + row * 1024);
    const int tid = threadIdx.x;  // 256
    float4 x = p[tid];
    float m = fmaxf(fmaxf(x.x, x.y), fmaxf(x.z, x.w));
    m = warpMax(m);
    __shared__ float sm[8], ss[8];
    if ((tid & 31) == 0) sm[tid >> 5] = m;
    __syncthreads();
    if (tid < 32) {
        float v = (tid < 8) ? sm[tid] : -1e30f;
        v = warpMax(v);
        if (tid == 0) sm[0] = v;
    }
    __syncthreads();
    m = sm[0];
    float e0 = __expf(x.x - m), e1 = __expf(x.y - m),
          e2 = __expf(x.z - m), e3 = __expf(x.w - m);
    float s = e0 + e1 + e2 + e3;
    s = warpSum(s);
    if ((tid & 31) == 0) ss[tid >> 5] = s;
    __syncthreads();
    if (tid < 32) {
        float v = (tid < 8) ? ss[tid] : 0.f;
        v = warpSum(v);
        if (tid == 0) ss[0] = v;
    }
    __syncthreads();
    const float inv = 1.0f / ss[0];
    p[tid] = make_float4(f2tf(e0 * inv), f2tf(e1 * inv),
                         f2tf(e2 * inv), f2tf(e3 * inv));
}

// ---------------- host side ---------------------------------------------------
extern "C" void kernel_launch(void* const* d_in, const int* in_sizes, int n_in,
                              void* d_out, int out_size) {
    const float* query = (const float*)d_in[0];
    const float* key   = (const float*)d_in[1];
    const float* value = (const float*)d_in[2];
    const float* Wq = (const float*)d_in[3];
    const float* bq = (const float*)d_in[4];
    const float* Wk = (const float*)d_in[5];
    const float* bk = (const float*)d_in[6];
    const float* Wv = (const float*)d_in[7];
    const float* bv = (const float*)d_in[8];
    const float* Wo = (const float*)d_in[9];
    const float* bo = (const float*)d_in[10];
    float* out = (float*)d_out;

    float *rin, *rw, *bias, *q, *k, *v, *w, *o;
    cudaGetSymbolAddress((void**)&rin, g_rin);
    cudaGetSymbolAddress((void**)&rw, g_rw);
    cudaGetSymbolAddress((void**)&bias, g_bias);
    cudaGetSymbolAddress((void**)&q, g_q);
    cudaGetSymbolAddress((void**)&k, g_k);
    cudaGetSymbolAddress((void**)&v, g_v);
    cudaGetSymbolAddress((void**)&w, g_w);
    cudaGetSymbolAddress((void**)&o, g_o);

    cudaFuncSetAttribute(gemm_qkv,
                         cudaFuncAttributeMaxDynamicSharedMemorySize, SMEM_BYTES);
    cudaFuncSetAttribute(gemm_k<false, false>,
                         cudaFuncAttributeMaxDynamicSharedMemorySize, SMEM_BYTES);
    cudaFuncSetAttribute(gemm_k<false, true>,
                         cudaFuncAttributeMaxDynamicSharedMemorySize, SMEM_BYTES);
    cudaFuncSetAttribute(gemm_k<true, false>,
                         cudaFuncAttributeMaxDynamicSharedMemorySize, SMEM_BYTES);

    round3<<<3 * 16384, 256>>>(query, key, value, rin);
    round4w<<<4 * 1024, 256>>>(Wq, Wk, Wv, Wo, rw);
    copy_bias<<<12, 256>>>(bq, bk, bv, bias);

    const long long MB = 1024LL * 1024LL;
    dim3 blk(256);

    // fused q/k/v projections (q,v transposed outputs)
    gemm_qkv<<<dim3(8, 128, 3), blk, SMEM_BYTES>>>(rin, rw, bias, q, k, v);

    // logits: w[b,i,s] = (1/32) sum_t qT[i, b*1024+t] * k[b*1024+s, t]
    gemm_k<false, false><<<dim3(8, 8, 16), blk, SMEM_BYTES>>>(
        q, k, nullptr, w, 1024, MB, MB, 16384, 1024, 1024, 0.03125f);

    softmax1024<<<16 * 1024, 256>>>(w);

    // o[b,i,e] = sum_s a[b,i,s] * vT[e, b*1024+s]
    gemm_k<false, true><<<dim3(8, 8, 16), blk, SMEM_BYTES>>>(
        w, v, nullptr, o, MB, 1024, MB, 1024, 16384, 1024, 1.0f);

    // out = o @ Wo^T + bo
    gemm_k<true, false><<<dim3(8, 128, 1), blk, SMEM_BYTES>>>(
        o, rw + 3 * MB, bo, out, 0, 0, 0, 1024, 1024, 1024, 1.0f);
}

// round 9
// speedup vs baseline: 1.5313x; 1.0968x over previous
#include <cuda_runtime.h>
#include <cstdint>
#include <math.h>

// ============================================================================
// CustomAttention B=16, T=S=E=1024 fp32. mma.sync tf32, cp.async 3-stage BK=32,
// ldmatrix fragments, all GEMMs K-major (q/v projections store transposed).
// 256-thread CTAs, block 128x128x32, 8 warps of 64x32, 2 CTAs/SM (16 warps/SM).
// R9: k-loop unrolled by 3 (compile-time ring index), prefetch issued between
// first fragment loads and first MMAs, prep kernels fused.
// ============================================================================

#define LDA 36                      // smem row stride (floats), K-major rows
#define LDB 36
#define AOP_BYTES (128 * LDA * 4)   // 18432
#define B_OFF_BYTES AOP_BYTES
#define STG_BYTES (2 * AOP_BYTES)   // 36864
#define SMEM_BYTES (3 * STG_BYTES)  // 110592

// ---------------- scratch (device globals; no allocation allowed) -----------
__device__ float g_rin[48u * 1024u * 1024u];  // rounded query|key|value
__device__ float g_rw [4u * 1024u * 1024u];   // rounded Wq|Wk|Wv|Wo
__device__ float g_bias[3 * 1024];            // bq|bk|bv
__device__ float g_q [16u * 1024u * 1024u];   // qT[i][b*1024+t]  (ld 16384)
__device__ float g_k [16u * 1024u * 1024u];   // k[b*1024+s][t]   (ld 1024)
__device__ float g_v [16u * 1024u * 1024u];   // vT[e][b*1024+s]  (ld 16384)
__device__ float g_w [16u * 1024u * 1024u];
__device__ float g_o [16u * 1024u * 1024u];

__device__ __forceinline__ float f2tf(float x) {
    unsigned u;
    asm("cvt.rna.tf32.f32 %0, %1;" : "=r"(u) : "f"(x));
    return __uint_as_float(u);
}
__device__ __forceinline__ void cpa16(uint32_t s, const float* g) {
    asm volatile("cp.async.cg.shared.global [%0], [%1], 16;" :: "r"(s), "l"(g));
}
#define CP_COMMIT() asm volatile("cp.async.commit_group;")
#define CP_WAIT1()  asm volatile("cp.async.wait_group 1;")

__device__ __forceinline__ void ldsm4(uint32_t* r, uint32_t addr) {
    asm volatile("ldmatrix.sync.aligned.m8n8.x4.shared.b16 {%0,%1,%2,%3}, [%4];"
                 : "=r"(r[0]), "=r"(r[1]), "=r"(r[2]), "=r"(r[3]) : "r"(addr));
}
__device__ __forceinline__ void mma8(float* d, const uint32_t* a,
                                     const uint32_t* b) {
    asm volatile(
        "mma.sync.aligned.m16n8k8.row.col.f32.tf32.tf32.f32 "
        "{%0,%1,%2,%3}, {%4,%5,%6,%7}, {%8,%9}, {%0,%1,%2,%3};"
        : "+f"(d[0]), "+f"(d[1]), "+f"(d[2]), "+f"(d[3])
        : "r"(a[0]), "r"(a[1]), "r"(a[2]), "r"(a[3]), "r"(b[0]), "r"(b[1]));
}

// ---------------- shared mainloop: 128x128 tile, K=1024, all K-major --------
// At = A + bm*sA (rows m, k contiguous); Bt = B + bn*sB (rows n, k contiguous)
// 256 threads: 8 warps, warp tile 64(M) x 32(N).
#define LOAD_FRAGS(STGOFF, K8, AA, BB)                                         \
    _Pragma("unroll") for (int mt = 0; mt < 4; mt++)                           \
        ldsm4(AA[mt], aLane + (STGOFF) + mt * (16 * LDA * 4) + (K8) * 32);     \
    _Pragma("unroll") for (int p = 0; p < 2; p++)                              \
        ldsm4(BB[p], bLane + (STGOFF) + p * (16 * LDB * 4) + (K8) * 32);

#define DO_MMAS(AA, BB)                                                        \
    _Pragma("unroll") for (int mt = 0; mt < 4; mt++)                           \
        _Pragma("unroll") for (int nt = 0; nt < 4; nt++)                       \
            mma8(acc[mt][nt], AA[mt], &BB[nt >> 1][(nt & 1) << 1]);

#define KTILE(CUR, PRE, KT, DOPF)                                              \
    do {                                                                       \
        CP_WAIT1();                                                            \
        __syncthreads();                                                       \
        {                                                                      \
            uint32_t a0[4][4], b0[2][4];                                       \
            LOAD_FRAGS((CUR) * STG_BYTES, 0, a0, b0)                           \
            if (DOPF) {                                                        \
                const int k0 = ((KT) + 2) << 5;                                \
                const uint32_t st = (PRE) * STG_BYTES;                         \
                _Pragma("unroll") for (int i = 0; i < 4; i++) {                \
                    cpa16(saA + st + i * (32 * LDA * 4), gA + k0 + i * 32LL * sA); \
                    cpa16(saB + st + i * (32 * LDB * 4), gB + k0 + i * 32LL * sB); \
                }                                                              \
            }                                                                  \
            CP_COMMIT();                                                       \
            DO_MMAS(a0, b0)                                                    \
        }                                                                      \
        _Pragma("unroll") for (int k8 = 1; k8 < 4; k8++) {                     \
            uint32_t a1[4][4], b1[2][4];                                       \
            LOAD_FRAGS((CUR) * STG_BYTES, k8, a1, b1)                          \
            DO_MMAS(a1, b1)                                                    \
        }                                                                      \
    } while (0)

__device__ __forceinline__ void gemm_main(const float* __restrict__ At,
                                          const float* __restrict__ Bt,
                                          int sA, int sB, float* sm,
                                          float (&acc)[4][4][4]) {
    const uint32_t smb = (uint32_t)__cvta_generic_to_shared(sm);
    const int tid = threadIdx.x, lane = tid & 31, warp = tid >> 5;
    const int wm = (warp & 1) << 6;        // 0 / 64
    const int wn = (warp >> 1) << 5;       // 0 / 32 / 64 / 96

    // cp.async lanes: row = tid>>3 (+32*i), quad = (tid&7)*4 floats
    const int rq = tid >> 3, qq = (tid & 7) << 2;
    const float* gA = At + (long long)rq * sA + qq;
    const float* gB = Bt + (long long)rq * sB + qq;
    const uint32_t saA = smb + (uint32_t)(rq * LDA + qq) * 4u;
    const uint32_t saB = smb + B_OFF_BYTES + (uint32_t)(rq * LDB + qq) * 4u;

    // LDSM lane addressing (8x8 b16 matrices over f32 data)
    const int seg = lane >> 3, li = lane & 7;
    const uint32_t aLane =
        smb + (uint32_t)((wm + ((seg & 1) << 3) + li) * LDA + ((seg >> 1) << 2)) * 4u;
    const uint32_t bLane =
        smb + B_OFF_BYTES +
        (uint32_t)((wn + ((seg >> 1) << 3) + li) * LDB + ((seg & 1) << 2)) * 4u;

    // prologue: stages 0,1 (tiles 0,1)
#pragma unroll
    for (int s = 0; s < 2; s++) {
        const uint32_t st = s * STG_BYTES;
        const int k0 = s * 32;
#pragma unroll
        for (int i = 0; i < 4; i++) {
            cpa16(saA + st + i * (32 * LDA * 4), gA + k0 + i * 32LL * sA);
            cpa16(saB + st + i * (32 * LDB * 4), gB + k0 + i * 32LL * sB);
        }
        CP_COMMIT();
    }

    // main: 30 tiles, ring index compile-time via 3x unroll
#pragma unroll 1
    for (int kt = 0; kt < 30; kt += 3) {
        KTILE(0, 2, kt, true);
        KTILE(1, 0, kt + 1, true);
        KTILE(2, 1, kt + 2, true);
    }
    // tail: tiles 30 (buf 0), 31 (buf 1); no prefetch (empty commits keep count)
    KTILE(0, 2, 30, false);
    KTILE(1, 0, 31, false);
}

// ---------------- standard GEMM: C[z][m][n] = scale*A.B^T (+bias) -----------
template <bool BIAS, bool ROUND>
__global__ void __launch_bounds__(256, 2)
gemm_k(const float* __restrict__ A, const float* __restrict__ B,
       const float* __restrict__ bias, float* __restrict__ C,
       long long bsA, long long bsB, long long bsC,
       int sA, int sB, int ldC, float scale) {
    extern __shared__ float sm[];
    const int bn = blockIdx.x << 7, bm = blockIdx.y << 7, z = blockIdx.z;
    const float* At = A + (long long)z * bsA + (long long)bm * sA;
    const float* Bt = B + (long long)z * bsB + (long long)bn * sB;

    float acc[4][4][4];
#pragma unroll
    for (int i = 0; i < 4; i++)
#pragma unroll
        for (int j = 0; j < 4; j++)
#pragma unroll
            for (int l = 0; l < 4; l++) acc[i][j][l] = 0.f;

    gemm_main(At, Bt, sA, sB, sm, acc);

    float* Cz = C + (long long)z * bsC;
    const int lane = threadIdx.x & 31, warp = threadIdx.x >> 5;
    const int wm = (warp & 1) << 6, wn = (warp >> 1) << 5;
    const int gr = lane >> 2, kr = lane & 3;
#pragma unroll
    for (int mt = 0; mt < 4; mt++) {
        const long long r0 = (long long)(bm + wm + mt * 16 + gr) * ldC;
#pragma unroll
        for (int nt = 0; nt < 4; nt++) {
            const int col = bn + wn + nt * 8 + kr * 2;
            float b0 = 0.f, b1 = 0.f;
            if (BIAS) {
                float2 bb = *(const float2*)(bias + col);
                b0 = bb.x; b1 = bb.y;
            }
            float x0 = acc[mt][nt][0] * scale + b0;
            float x1 = acc[mt][nt][1] * scale + b1;
            float x2 = acc[mt][nt][2] * scale + b0;
            float x3 = acc[mt][nt][3] * scale + b1;
            if (ROUND) { x0 = f2tf(x0); x1 = f2tf(x1); x2 = f2tf(x2); x3 = f2tf(x3); }
            *(float2*)&Cz[r0 + col] = make_float2(x0, x1);
            *(float2*)&Cz[r0 + 8LL * ldC + col] = make_float2(x2, x3);
        }
    }
}

// ---------------- fused QKV projection: z=0 qT, z=1 k, z=2 vT ----------------
__global__ void __launch_bounds__(256, 2)
gemm_qkv(const float* __restrict__ Ain, const float* __restrict__ W,
         const float* __restrict__ biases,
         float* __restrict__ Cq, float* __restrict__ Ck, float* __restrict__ Cv) {
    extern __shared__ float sm[];
    const int bn = blockIdx.x << 7, bm = blockIdx.y << 7, z = blockIdx.z;
    const float* At = Ain + (long long)z * (16LL << 20) + (long long)bm * 1024;
    const float* Bt = W + (long long)z * (1LL << 20) + (long long)bn * 1024;
    const float* bias = biases + z * 1024;

    float acc[4][4][4];
#pragma unroll
    for (int i = 0; i < 4; i++)
#pragma unroll
        for (int j = 0; j < 4; j++)
#pragma unroll
            for (int l = 0; l < 4; l++) acc[i][j][l] = 0.f;

    gemm_main(At, Bt, 1024, 1024, sm, acc);

    const int lane = threadIdx.x & 31, warp = threadIdx.x >> 5;
    const int wm = (warp & 1) << 6, wn = (warp >> 1) << 5;
    const int gr = lane >> 2, kr = lane & 3;

    if (z == 1) {  // normal store: k[m][n], ld 1024
#pragma unroll
        for (int mt = 0; mt < 4; mt++) {
            const long long r0 = (long long)(bm + wm + mt * 16 + gr) * 1024;
#pragma unroll
            for (int nt = 0; nt < 4; nt++) {
                const int col = bn + wn + nt * 8 + kr * 2;
                float2 bb = *(const float2*)(bias + col);
                float x0 = f2tf(acc[mt][nt][0] + bb.x);
                float x1 = f2tf(acc[mt][nt][1] + bb.y);
                float x2 = f2tf(acc[mt][nt][2] + bb.x);
                float x3 = f2tf(acc[mt][nt][3] + bb.y);
                *(float2*)&Ck[r0 + col] = make_float2(x0, x1);
                *(float2*)&Ck[r0 + 8LL * 1024 + col] = make_float2(x2, x3);
            }
        }
    } else {       // transposed store: CT[n][m], ld 16384
        float* CT = (z == 0) ? Cq : Cv;
#pragma unroll
        for (int mt = 0; mt < 4; mt++) {
            const int row = bm + wm + mt * 16 + gr;
#pragma unroll
            for (int nt = 0; nt < 4; nt++) {
                const int col = bn + wn + nt * 8 + kr * 2;
                float2 bb = *(const float2*)(bias + col);
                float x0 = f2tf(acc[mt][nt][0] + bb.x);
                float x1 = f2tf(acc[mt][nt][1] + bb.y);
                float x2 = f2tf(acc[mt][nt][2] + bb.x);
                float x3 = f2tf(acc[mt][nt][3] + bb.y);
                CT[(long long)col * 16384 + row] = x0;
                CT[(long long)(col + 1) * 16384 + row] = x1;
                CT[(long long)col * 16384 + row + 8] = x2;
                CT[(long long)(col + 1) * 16384 + row + 8] = x3;
            }
        }
    }
}

// ---------------- fused prep: round q/k/v + weights, copy biases ------------
__global__ void prep(const float* __restrict__ q, const float* __restrict__ k,
                     const float* __restrict__ v,
                     const float* __restrict__ w0, const float* __restrict__ w1,
                     const float* __restrict__ w2, const float* __restrict__ w3,
                     const float* __restrict__ b0, const float* __restrict__ b1,
                     const float* __restrict__ b2,
                     float* __restrict__ rin, float* __restrict__ rw,
                     float* __restrict__ bias) {
    const int b = blockIdx.x;
    if (b < 49152) {                       // 3 x 16M inputs
        const int t = b >> 14;
        const int i = ((b & 16383) << 10) + (threadIdx.x << 2);
        const float* in = (t == 0) ? q : (t == 1) ? k : v;
        float4 x = *(const float4*)(in + i);
        x.x = f2tf(x.x); x.y = f2tf(x.y); x.z = f2tf(x.z); x.w = f2tf(x.w);
        *(float4*)(rin + (((long long)t) << 24) + i) = x;
    } else if (b < 53248) {                // 4 x 1M weights
        const int bb = b - 49152;
        const int t = bb >> 10;
        const int i = ((bb & 1023) << 10) + (threadIdx.x << 2);
        const float* in = (t == 0) ? w0 : (t == 1) ? w1 : (t == 2) ? w2 : w3;
        float4 x = *(const float4*)(in + i);
        x.x = f2tf(x.x); x.y = f2tf(x.y); x.z = f2tf(x.z); x.w = f2tf(x.w);
        *(float4*)(rw + (t << 20) + i) = x;
    } else {                               // 3 x 1024 biases
        const int idx = ((b - 53248) << 8) + threadIdx.x;   // 0..3071
        const float* s = (idx < 1024) ? b0 : (idx < 2048) ? b1 : b2;
        bias[idx] = s[idx & 1023];
    }
}

// ---------------- softmax over rows of 1024, in place, rounds output ---------
__device__ __forceinline__ float warpMax(float v) {
#pragma unroll
    for (int o = 16; o; o >>= 1) v = fmaxf(v, __shfl_xor_sync(0xffffffffu, v, o));
    return v;
}
__device__ __forceinline__ float warpSum(float v) {
#pragma unroll
    for (int o = 16; o; o >>= 1) v += __shfl_xor_sync(0xffffffffu, v, o);
    return v;
}
__global__ void softmax1024(float* __restrict__ W) {
    const long long row = blockIdx.x;
    float4* p = (float4*)(W + row * 1024);
    const int tid = threadIdx.x;  // 256
    float4 x = p[tid];
    float m = fmaxf(fmaxf(x.x, x.y), fmaxf(x.z, x.w));
    m = warpMax(m);
    __shared__ float sm[8], ss[8];
    if ((tid & 31) == 0) sm[tid >> 5] = m;
    __syncthreads();
    if (tid < 32) {
        float v = (tid < 8) ? sm[tid] : -1e30f;
        v = warpMax(v);
        if (tid == 0) sm[0] = v;
    }
    __syncthreads();
    m = sm[0];
    float e0 = __expf(x.x - m), e1 = __expf(x.y - m),
          e2 = __expf(x.z - m), e3 = __expf(x.w - m);
    float s = e0 + e1 + e2 + e3;
    s = warpSum(s);
    if ((tid & 31) == 0) ss[tid >> 5] = s;
    __syncthreads();
    if (tid < 32) {
        float v = (tid < 8) ? ss[tid] : 0.f;
        v = warpSum(v);
        if (tid == 0) ss[0] = v;
    }
    __syncthreads();
    const float inv = 1.0f / ss[0];
    p[tid] = make_float4(f2tf(e0 * inv), f2tf(e1 * inv),
                         f2tf(e2 * inv), f2tf(e3 * inv));
}

// ---------------- host side ---------------------------------------------------
extern "C" void kernel_launch(void* const* d_in, const int* in_sizes, int n_in,
                              void* d_out, int out_size) {
    const float* query = (const float*)d_in[0];
    const float* key   = (const float*)d_in[1];
    const float* value = (const float*)d_in[2];
    const float* Wq = (const float*)d_in[3];
    const float* bq = (const float*)d_in[4];
    const float* Wk = (const float*)d_in[5];
    const float* bk = (const float*)d_in[6];
    const float* Wv = (const float*)d_in[7];
    const float* bv = (const float*)d_in[8];
    const float* Wo = (const float*)d_in[9];
    const float* bo = (const float*)d_in[10];
    float* out = (float*)d_out;

    float *rin, *rw, *bias, *q, *k, *v, *w, *o;
    cudaGetSymbolAddress((void**)&rin, g_rin);
    cudaGetSymbolAddress((void**)&rw, g_rw);
    cudaGetSymbolAddress((void**)&bias, g_bias);
    cudaGetSymbolAddress((void**)&q, g_q);
    cudaGetSymbolAddress((void**)&k, g_k);
    cudaGetSymbolAddress((void**)&v, g_v);
    cudaGetSymbolAddress((void**)&w, g_w);
    cudaGetSymbolAddress((void**)&o, g_o);

    cudaFuncSetAttribute(gemm_qkv,
                         cudaFuncAttributeMaxDynamicSharedMemorySize, SMEM_BYTES);
    cudaFuncSetAttribute(gemm_k<false, false>,
                         cudaFuncAttributeMaxDynamicSharedMemorySize, SMEM_BYTES);
    cudaFuncSetAttribute(gemm_k<false, true>,
                         cudaFuncAttributeMaxDynamicSharedMemorySize, SMEM_BYTES);
    cudaFuncSetAttribute(gemm_k<true, false>,
                         cudaFuncAttributeMaxDynamicSharedMemorySize, SMEM_BYTES);

    prep<<<53260, 256>>>(query, key, value, Wq, Wk, Wv, Wo, bq, bk, bv,
                         rin, rw, bias);

    const long long MB = 1024LL * 1024LL;
    dim3 blk(256);

    // fused q/k/v projections (q,v transposed outputs)
    gemm_qkv<<<dim3(8, 128, 3), blk, SMEM_BYTES>>>(rin, rw, bias, q, k, v);

    // logits: w[b,i,s] = (1/32) sum_t qT[i, b*1024+t] * k[b*1024+s, t]
    gemm_k<false, false><<<dim3(8, 8, 16), blk, SMEM_BYTES>>>(
        q, k, nullptr, w, 1024, MB, MB, 16384, 1024, 1024, 0.03125f);

    softmax1024<<<16 * 1024, 256>>>(w);

    // o[b,i,e] = sum_s a[b,i,s] * vT[e, b*1024+s]
    gemm_k<false, true><<<dim3(8, 8, 16), blk, SMEM_BYTES>>>(
        w, v, nullptr, o, MB, 1024, MB, 1024, 16384, 1024, 1.0f);

    // out = o @ Wo^T + bo
    gemm_k<true, false><<<dim3(8, 128, 1), blk, SMEM_BYTES>>>(
        o, rw + 3 * MB, bo, out, 0, 0, 0, 1024, 1024, 1024, 1.0f);
}

// round 10
// speedup vs baseline: 1.6998x; 1.1100x over previous
#include <cuda_runtime.h>
#include <cstdint>
#include <math.h>

// ============================================================================
// CustomAttention B=16, T=S=E=1024 fp32. mma.sync tf32, cp.async 3-stage BK=32,
// ldmatrix fragments, all GEMMs K-major (q/v projections store transposed).
// 256-thread CTAs, block 128x128x32, 8 warps of 64x32, 2 CTAs/SM (16 warps/SM).
// R10: B-fragment double buffering inside the tile, cp.async issue spread
// across k8 sections (smooth L1 read/write interleave).
// ============================================================================

#define LDA 36                      // smem row stride (floats), K-major rows
#define LDB 36
#define AOP_BYTES (128 * LDA * 4)   // 18432
#define B_OFF_BYTES AOP_BYTES
#define STG_BYTES (2 * AOP_BYTES)   // 36864
#define SMEM_BYTES (3 * STG_BYTES)  // 110592

// ---------------- scratch (device globals; no allocation allowed) -----------
__device__ float g_rin[48u * 1024u * 1024u];  // rounded query|key|value
__device__ float g_rw [4u * 1024u * 1024u];   // rounded Wq|Wk|Wv|Wo
__device__ float g_bias[3 * 1024];            // bq|bk|bv
__device__ float g_q [16u * 1024u * 1024u];   // qT[i][b*1024+t]  (ld 16384)
__device__ float g_k [16u * 1024u * 1024u];   // k[b*1024+s][t]   (ld 1024)
__device__ float g_v [16u * 1024u * 1024u];   // vT[e][b*1024+s]  (ld 16384)
__device__ float g_w [16u * 1024u * 1024u];
__device__ float g_o [16u * 1024u * 1024u];

__device__ __forceinline__ float f2tf(float x) {
    unsigned u;
    asm("cvt.rna.tf32.f32 %0, %1;" : "=r"(u) : "f"(x));
    return __uint_as_float(u);
}
__device__ __forceinline__ void cpa16(uint32_t s, const float* g) {
    asm volatile("cp.async.cg.shared.global [%0], [%1], 16;" :: "r"(s), "l"(g));
}
#define CP_COMMIT() asm volatile("cp.async.commit_group;")
#define CP_WAIT1()  asm volatile("cp.async.wait_group 1;")

__device__ __forceinline__ void ldsm4(uint32_t* r, uint32_t addr) {
    asm volatile("ldmatrix.sync.aligned.m8n8.x4.shared.b16 {%0,%1,%2,%3}, [%4];"
                 : "=r"(r[0]), "=r"(r[1]), "=r"(r[2]), "=r"(r[3]) : "r"(addr));
}
__device__ __forceinline__ void mma8(float* d, const uint32_t* a,
                                     const uint32_t* b) {
    asm volatile(
        "mma.sync.aligned.m16n8k8.row.col.f32.tf32.tf32.f32 "
        "{%0,%1,%2,%3}, {%4,%5,%6,%7}, {%8,%9}, {%0,%1,%2,%3};"
        : "+f"(d[0]), "+f"(d[1]), "+f"(d[2]), "+f"(d[3])
        : "r"(a[0]), "r"(a[1]), "r"(a[2]), "r"(a[3]), "r"(b[0]), "r"(b[1]));
}

// ---------------- shared mainloop: 128x128 tile, K=1024, all K-major --------
// At = A + bm*sA (rows m, k contiguous); Bt = B + bn*sB (rows n, k contiguous)
// 256 threads: 8 warps, warp tile 64(M) x 32(N).
#define LOAD_A(STGOFF, K8, AA)                                                 \
    _Pragma("unroll") for (int mt = 0; mt < 4; mt++)                           \
        ldsm4(AA[mt], aLane + (STGOFF) + mt * (16 * LDA * 4) + (K8) * 32);

#define LOAD_B(STGOFF, K8, BB)                                                 \
    _Pragma("unroll") for (int p = 0; p < 2; p++)                              \
        ldsm4(BB[p], bLane + (STGOFF) + p * (16 * LDB * 4) + (K8) * 32);

#define DO_MMAS(AA, BB)                                                        \
    _Pragma("unroll") for (int mt = 0; mt < 4; mt++)                           \
        _Pragma("unroll") for (int nt = 0; nt < 4; nt++)                       \
            mma8(acc[mt][nt], AA[mt], &BB[nt >> 1][(nt & 1) << 1]);

// Per k8 section: prefetch next B frags, issue 2 cp.async of next stage,
// run MMAs on current frags, then reload A for the next section.
#define KTILE(CUR, PRE, KT, DOPF)                                              \
    do {                                                                       \
        CP_WAIT1();                                                            \
        __syncthreads();                                                       \
        uint32_t a[4][4], b[2][2][4];                                          \
        LOAD_B((CUR) * STG_BYTES, 0, b[0])                                     \
        LOAD_A((CUR) * STG_BYTES, 0, a)                                        \
        _Pragma("unroll") for (int k8 = 0; k8 < 4; k8++) {                     \
            if (k8 < 3) { LOAD_B((CUR) * STG_BYTES, k8 + 1, b[(k8 + 1) & 1]) } \
            if (DOPF) {                                                        \
                const int k0 = ((KT) + 2) << 5;                                \
                const uint32_t st = (PRE) * STG_BYTES;                         \
                cpa16(saA + st + k8 * (32 * LDA * 4), gA + k0 + k8 * 32LL * sA); \
                cpa16(saB + st + k8 * (32 * LDB * 4), gB + k0 + k8 * 32LL * sB); \
            }                                                                  \
            if (k8 == 3) CP_COMMIT();                                          \
            DO_MMAS(a, b[k8 & 1])                                              \
            if (k8 < 3) { LOAD_A((CUR) * STG_BYTES, k8 + 1, a) }               \
        }                                                                      \
    } while (0)

__device__ __forceinline__ void gemm_main(const float* __restrict__ At,
                                          const float* __restrict__ Bt,
                                          int sA, int sB, float* sm,
                                          float (&acc)[4][4][4]) {
    const uint32_t smb = (uint32_t)__cvta_generic_to_shared(sm);
    const int tid = threadIdx.x, lane = tid & 31, warp = tid >> 5;
    const int wm = (warp & 1) << 6;        // 0 / 64
    const int wn = (warp >> 1) << 5;       // 0 / 32 / 64 / 96

    // cp.async lanes: row = tid>>3 (+32*i), quad = (tid&7)*4 floats
    const int rq = tid >> 3, qq = (tid & 7) << 2;
    const float* gA = At + (long long)rq * sA + qq;
    const float* gB = Bt + (long long)rq * sB + qq;
    const uint32_t saA = smb + (uint32_t)(rq * LDA + qq) * 4u;
    const uint32_t saB = smb + B_OFF_BYTES + (uint32_t)(rq * LDB + qq) * 4u;

    // LDSM lane addressing (8x8 b16 matrices over f32 data)
    const int seg = lane >> 3, li = lane & 7;
    const uint32_t aLane =
        smb + (uint32_t)((wm + ((seg & 1) << 3) + li) * LDA + ((seg >> 1) << 2)) * 4u;
    const uint32_t bLane =
        smb + B_OFF_BYTES +
        (uint32_t)((wn + ((seg >> 1) << 3) + li) * LDB + ((seg & 1) << 2)) * 4u;

    // prologue: stages 0,1 (tiles 0,1)
#pragma unroll
    for (int s = 0; s < 2; s++) {
        const uint32_t st = s * STG_BYTES;
        const int k0 = s * 32;
#pragma unroll
        for (int i = 0; i < 4; i++) {
            cpa16(saA + st + i * (32 * LDA * 4), gA + k0 + i * 32LL * sA);
            cpa16(saB + st + i * (32 * LDB * 4), gB + k0 + i * 32LL * sB);
        }
        CP_COMMIT();
    }

    // main: 30 tiles, ring index compile-time via 3x unroll
#pragma unroll 1
    for (int kt = 0; kt < 30; kt += 3) {
        KTILE(0, 2, kt, true);
        KTILE(1, 0, kt + 1, true);
        KTILE(2, 1, kt + 2, true);
    }
    // tail: tiles 30 (buf 0), 31 (buf 1); no prefetch (empty commits keep count)
    KTILE(0, 2, 30, false);
    KTILE(1, 0, 31, false);
}

// ---------------- standard GEMM: C[z][m][n] = scale*A.B^T (+bias) -----------
template <bool BIAS, bool ROUND>
__global__ void __launch_bounds__(256, 2)
gemm_k(const float* __restrict__ A, const float* __restrict__ B,
       const float* __restrict__ bias, float* __restrict__ C,
       long long bsA, long long bsB, long long bsC,
       int sA, int sB, int ldC, float scale) {
    extern __shared__ float sm[];
    const int bn = blockIdx.x << 7, bm = blockIdx.y << 7, z = blockIdx.z;
    const float* At = A + (long long)z * bsA + (long long)bm * sA;
    const float* Bt = B + (long long)z * bsB + (long long)bn * sB;

    float acc[4][4][4];
#pragma unroll
    for (int i = 0; i < 4; i++)
#pragma unroll
        for (int j = 0; j < 4; j++)
#pragma unroll
            for (int l = 0; l < 4; l++) acc[i][j][l] = 0.f;

    gemm_main(At, Bt, sA, sB, sm, acc);

    float* Cz = C + (long long)z * bsC;
    const int lane = threadIdx.x & 31, warp = threadIdx.x >> 5;
    const int wm = (warp & 1) << 6, wn = (warp >> 1) << 5;
    const int gr = lane >> 2, kr = lane & 3;
#pragma unroll
    for (int mt = 0; mt < 4; mt++) {
        const long long r0 = (long long)(bm + wm + mt * 16 + gr) * ldC;
#pragma unroll
        for (int nt = 0; nt < 4; nt++) {
            const int col = bn + wn + nt * 8 + kr * 2;
            float b0 = 0.f, b1 = 0.f;
            if (BIAS) {
                float2 bb = *(const float2*)(bias + col);
                b0 = bb.x; b1 = bb.y;
            }
            float x0 = acc[mt][nt][0] * scale + b0;
            float x1 = acc[mt][nt][1] * scale + b1;
            float x2 = acc[mt][nt][2] * scale + b0;
            float x3 = acc[mt][nt][3] * scale + b1;
            if (ROUND) { x0 = f2tf(x0); x1 = f2tf(x1); x2 = f2tf(x2); x3 = f2tf(x3); }
            *(float2*)&Cz[r0 + col] = make_float2(x0, x1);
            *(float2*)&Cz[r0 + 8LL * ldC + col] = make_float2(x2, x3);
        }
    }
}

// ---------------- fused QKV projection: z=0 qT, z=1 k, z=2 vT ----------------
__global__ void __launch_bounds__(256, 2)
gemm_qkv(const float* __restrict__ Ain, const float* __restrict__ W,
         const float* __restrict__ biases,
         float* __restrict__ Cq, float* __restrict__ Ck, float* __restrict__ Cv) {
    extern __shared__ float sm[];
    const int bn = blockIdx.x << 7, bm = blockIdx.y << 7, z = blockIdx.z;
    const float* At = Ain + (long long)z * (16LL << 20) + (long long)bm * 1024;
    const float* Bt = W + (long long)z * (1LL << 20) + (long long)bn * 1024;
    const float* bias = biases + z * 1024;

    float acc[4][4][4];
#pragma unroll
    for (int i = 0; i < 4; i++)
#pragma unroll
        for (int j = 0; j < 4; j++)
#pragma unroll
            for (int l = 0; l < 4; l++) acc[i][j][l] = 0.f;

    gemm_main(At, Bt, 1024, 1024, sm, acc);

    const int lane = threadIdx.x & 31, warp = threadIdx.x >> 5;
    const int wm = (warp & 1) << 6, wn = (warp >> 1) << 5;
    const int gr = lane >> 2, kr = lane & 3;

    if (z == 1) {  // normal store: k[m][n], ld 1024
#pragma unroll
        for (int mt = 0; mt < 4; mt++) {
            const long long r0 = (long long)(bm + wm + mt * 16 + gr) * 1024;
#pragma unroll
            for (int nt = 0; nt < 4; nt++) {
                const int col = bn + wn + nt * 8 + kr * 2;
                float2 bb = *(const float2*)(bias + col);
                float x0 = f2tf(acc[mt][nt][0] + bb.x);
                float x1 = f2tf(acc[mt][nt][1] + bb.y);
                float x2 = f2tf(acc[mt][nt][2] + bb.x);
                float x3 = f2tf(acc[mt][nt][3] + bb.y);
                *(float2*)&Ck[r0 + col] = make_float2(x0, x1);
                *(float2*)&Ck[r0 + 8LL * 1024 + col] = make_float2(x2, x3);
            }
        }
    } else {       // transposed store: CT[n][m], ld 16384
        float* CT = (z == 0) ? Cq : Cv;
#pragma unroll
        for (int mt = 0; mt < 4; mt++) {
            const int row = bm + wm + mt * 16 + gr;
#pragma unroll
            for (int nt = 0; nt < 4; nt++) {
                const int col = bn + wn + nt * 8 + kr * 2;
                float2 bb = *(const float2*)(bias + col);
                float x0 = f2tf(acc[mt][nt][0] + bb.x);
                float x1 = f2tf(acc[mt][nt][1] + bb.y);
                float x2 = f2tf(acc[mt][nt][2] + bb.x);
                float x3 = f2tf(acc[mt][nt][3] + bb.y);
                CT[(long long)col * 16384 + row] = x0;
                CT[(long long)(col + 1) * 16384 + row] = x1;
                CT[(long long)col * 16384 + row + 8] = x2;
                CT[(long long)(col + 1) * 16384 + row + 8] = x3;
            }
        }
    }
}

// ---------------- fused prep: round q/k/v + weights, copy biases ------------
__global__ void prep(const float* __restrict__ q, const float* __restrict__ k,
                     const float* __restrict__ v,
                     const float* __restrict__ w0, const float* __restrict__ w1,
                     const float* __restrict__ w2, const float* __restrict__ w3,
                     const float* __restrict__ b0, const float* __restrict__ b1,
                     const float* __restrict__ b2,
                     float* __restrict__ rin, float* __restrict__ rw,
                     float* __restrict__ bias) {
    const int b = blockIdx.x;
    if (b < 49152) {                       // 3 x 16M inputs
        const int t = b >> 14;
        const int i = ((b & 16383) << 10) + (threadIdx.x << 2);
        const float* in = (t == 0) ? q : (t == 1) ? k : v;
        float4 x = *(const float4*)(in + i);
        x.x = f2tf(x.x); x.y = f2tf(x.y); x.z = f2tf(x.z); x.w = f2tf(x.w);
        *(float4*)(rin + (((long long)t) << 24) + i) = x;
    } else if (b < 53248) {                // 4 x 1M weights
        const int bb = b - 49152;
        const int t = bb >> 10;
        const int i = ((bb & 1023) << 10) + (threadIdx.x << 2);
        const float* in = (t == 0) ? w0 : (t == 1) ? w1 : (t == 2) ? w2 : w3;
        float4 x = *(const float4*)(in + i);
        x.x = f2tf(x.x); x.y = f2tf(x.y); x.z = f2tf(x.z); x.w = f2tf(x.w);
        *(float4*)(rw + (t << 20) + i) = x;
    } else {                               // 3 x 1024 biases
        const int idx = ((b - 53248) << 8) + threadIdx.x;   // 0..3071
        const float* s = (idx < 1024) ? b0 : (idx < 2048) ? b1 : b2;
        bias[idx] = s[idx & 1023];
    }
}

// ---------------- softmax over rows of 1024, in place, rounds output ---------
__device__ __forceinline__ float warpMax(float v) {
#pragma unroll
    for (int o = 16; o; o >>= 1) v = fmaxf(v, __shfl_xor_sync(0xffffffffu, v, o));
    return v;
}
__device__ __forceinline__ float warpSum(float v) {
#pragma unroll
    for (int o = 16; o; o >>= 1) v += __shfl_xor_sync(0xffffffffu, v, o);
    return v;
}
__global__ void softmax1024(float* __restrict__ W) {
    const long long row = blockIdx.x;
    float4* p = (float4*)(W + row * 1024);
    const int tid = threadIdx.x;  // 256
    float4 x = p[tid];
    float m = fmaxf(fmaxf(x.x, x.y), fmaxf(x.z, x.w));
    m = warpMax(m);
    __shared__ float sm[8], ss[8];
    if ((tid & 31) == 0) sm[tid >> 5] = m;
    __syncthreads();
    if (tid < 32) {
        float v = (tid < 8) ? sm[tid] : -1e30f;
        v = warpMax(v);
        if (tid == 0) sm[0] = v;
    }
    __syncthreads();
    m = sm[0];
    float e0 = __expf(x.x - m), e1 = __expf(x.y - m),
          e2 = __expf(x.z - m), e3 = __expf(x.w - m);
    float s = e0 + e1 + e2 + e3;
    s = warpSum(s);
    if ((tid & 31) == 0) ss[tid >> 5] = s;
    __syncthreads();
    if (tid < 32) {
        float v = (tid < 8) ? ss[tid] : 0.f;
        v = warpSum(v);
        if (tid == 0) ss[0] = v;
    }
    __syncthreads();
    const float inv = 1.0f / ss[0];
    p[tid] = make_float4(f2tf(e0 * inv), f2tf(e1 * inv),
                         f2tf(e2 * inv), f2tf(e3 * inv));
}

// ---------------- host side ---------------------------------------------------
extern "C" void kernel_launch(void* const* d_in, const int* in_sizes, int n_in,
                              void* d_out, int out_size) {
    const float* query = (const float*)d_in[0];
    const float* key   = (const float*)d_in[1];
    const float* value = (const float*)d_in[2];
    const float* Wq = (const float*)d_in[3];
    const float* bq = (const float*)d_in[4];
    const float* Wk = (const float*)d_in[5];
    const float* bk = (const float*)d_in[6];
    const float* Wv = (const float*)d_in[7];
    const float* bv = (const float*)d_in[8];
    const float* Wo = (const float*)d_in[9];
    const float* bo = (const float*)d_in[10];
    float* out = (float*)d_out;

    float *rin, *rw, *bias, *q, *k, *v, *w, *o;
    cudaGetSymbolAddress((void**)&rin, g_rin);
    cudaGetSymbolAddress((void**)&rw, g_rw);
    cudaGetSymbolAddress((void**)&bias, g_bias);
    cudaGetSymbolAddress((void**)&q, g_q);
    cudaGetSymbolAddress((void**)&k, g_k);
    cudaGetSymbolAddress((void**)&v, g_v);
    cudaGetSymbolAddress((void**)&w, g_w);
    cudaGetSymbolAddress((void**)&o, g_o);

    cudaFuncSetAttribute(gemm_qkv,
                         cudaFuncAttributeMaxDynamicSharedMemorySize, SMEM_BYTES);
    cudaFuncSetAttribute(gemm_k<false, false>,
                         cudaFuncAttributeMaxDynamicSharedMemorySize, SMEM_BYTES);
    cudaFuncSetAttribute(gemm_k<false, true>,
                         cudaFuncAttributeMaxDynamicSharedMemorySize, SMEM_BYTES);
    cudaFuncSetAttribute(gemm_k<true, false>,
                         cudaFuncAttributeMaxDynamicSharedMemorySize, SMEM_BYTES);

    prep<<<53260, 256>>>(query, key, value, Wq, Wk, Wv, Wo, bq, bk, bv,
                         rin, rw, bias);

    const long long MB = 1024LL * 1024LL;
    dim3 blk(256);

    // fused q/k/v projections (q,v transposed outputs)
    gemm_qkv<<<dim3(8, 128, 3), blk, SMEM_BYTES>>>(rin, rw, bias, q, k, v);

    // logits: w[b,i,s] = (1/32) sum_t qT[i, b*1024+t] * k[b*1024+s, t]
    gemm_k<false, false><<<dim3(8, 8, 16), blk, SMEM_BYTES>>>(
        q, k, nullptr, w, 1024, MB, MB, 16384, 1024, 1024, 0.03125f);

    softmax1024<<<16 * 1024, 256>>>(w);

    // o[b,i,e] = sum_s a[b,i,s] * vT[e, b*1024+s]
    gemm_k<false, true><<<dim3(8, 8, 16), blk, SMEM_BYTES>>>(
        w, v, nullptr, o, MB, 1024, MB, 1024, 16384, 1024, 1.0f);

    // out = o @ Wo^T + bo
    gemm_k<true, false><<<dim3(8, 128, 1), blk, SMEM_BYTES>>>(
        o, rw + 3 * MB, bo, out, 0, 0, 0, 1024, 1024, 1024, 1.0f);
}